// round 12
// baseline (speedup 1.0000x reference)
#include <cuda_runtime.h>
#include <math.h>

#define T_STEPS   32768
#define N_NEUR    1024
#define FILT_LEN  200
#define THREADS   256
#define CHUNK     1024
#define NCH       (T_STEPS / CHUNK)
#define WIN       128
#define FTAB      1024
#define MAXSPK    4096

#define LOG_DT_F      (-6.907755278982137f)
#define NOISE_SIGMA_F (0.2f)
#define INH_FACTOR_F  (0.8187307530779818f)
#define INH_INC_F     (3000.0f)
#define SLIMC         (8.00536f)   // ln(3000) - 1e-3 (conservative candidate floor)
#define NEG_INF       (__int_as_float(0xff800000))

// scratch (no cudaMalloc allowed)
__device__ float          g_thr[T_STEPS];
__device__ float          g_q[T_STEPS];       // ln(thr) + 0.2*(t - chunk_base), -inf if thr<=0
__device__ unsigned short g_loc[T_STEPS];
__device__ int            g_cnt[NCH * 32];    // one counter per 128B line
__device__ float          g_filt[FILT_LEN];   // FIR taps
__device__ int            g_spk_t[MAXSPK];    // spike times
__device__ float          g_spk_a[MAXSPK];    // post-spike amplitudes

__global__ void init_kernel() {
    const int i = threadIdx.x;
    if (i < NCH * 32) g_cnt[i] = 0;
    if (i < FILT_LEN) g_filt[i] = expf(-((float)i) * 0.05f);
}

// ---------------------------------------------------------------------------
// Fused kernel. Block 0 = persistent scanner; blocks 1..T_STEPS = producers.
//
// Semantics (reference): spike_t = (inh_t < thr_t); inh_{t+1} = inh_t*F +
// 3000*spike_t; outputs inhibition[t] = inh_{t+1}. With A = inh_{s+1} stored
// at each spike s: inh_t = A * F^(t-s-1) for s < t <= next spike.   <-- R11
// fix: verification exponent is (tc - s_abs - 1), and the log-space candidate
// floor ramps from (s_abs + 1).
//
// Scanner phase 1: between spikes the log-space decision state is CONSTANT:
// spike at t  <=>  ln(thr)+0.2(t-cb) > ln(A)+0.2(s+1-cb). Each round tests
// 128 positions (LDS.128/lane + 4 ballots) against the conservative constant
// Slim = ln(3000)-eps+0.2(s+1-cb); the first candidate is exactly verified as
// fl(A*F^(tc-s-1)) < thr and the amplitude update fl(fl(w*F)+3000) happens
// off the position chain. Phase 2 reconstructs inhibition + scatters spikes.
// ---------------------------------------------------------------------------
__global__ void __launch_bounds__(THREADS)
fused_kernel(const float* __restrict__ inputs,
             const float* __restrict__ noise_rand,
             const float* __restrict__ u_mult,
             const float* __restrict__ rand_val,
             float* __restrict__ out)
{
    const int tid  = threadIdx.x;
    const int lane = tid & 31;
    const unsigned FULL = 0xffffffffu;
    const size_t IDX_INH = (size_t)T_STEPS * N_NEUR;

    __shared__ float s_q[2][CHUNK + WIN];   // pads [CHUNK, CHUNK+WIN) = -inf forever
    __shared__ float s_th[2][CHUNK];
    __shared__ float s_fp[FTAB + 1];
    __shared__ int   s_nspk;
    __shared__ float s_ns[8];
    __shared__ float s_wsum[8];
    __shared__ int   s_cnt[8];

    if (blockIdx.x != 0) {
        // =================== PRODUCER: row t = blockIdx.x - 1 ===============
        const int t   = blockIdx.x - 1;
        const int wid = tid >> 5;

        const float4 x4 =
            reinterpret_cast<const float4*>(inputs)[(size_t)t * (N_NEUR / 4) + tid];

        // noise tap (table'd FIR)
        float prod = 0.0f;
        if (tid < FILT_LEN) {
            int idx = t - tid;
            if (idx >= 0) prod = (noise_rand[idx] * NOISE_SIGMA_F) * g_filt[tid];
        }

        // unshifted exps (x ~ N(0,1): e^x <= ~110, no overflow; ratios exact)
        const float e0 = __expf(x4.x);
        const float e1 = __expf(x4.y);
        const float e2 = __expf(x4.z);
        const float e3 = __expf(x4.w);
        const float p0 = e0;
        const float p1 = p0 + e1;
        const float p2 = p1 + e2;
        const float p3 = p2 + e3;

        // warp: inclusive scan of p3 + butterfly reduce of noise prod
        float incl = p3;
        #pragma unroll
        for (int o = 1; o < 32; o <<= 1) {
            float n = __shfl_up_sync(FULL, incl, o);
            if (lane >= o) incl += n;
            prod += __shfl_xor_sync(FULL, prod, o);
        }
        if (lane == 31) s_wsum[wid] = incl;
        if (lane == 0)  s_ns[wid]   = prod;
        __syncthreads();

        float warp_off = 0.0f, stot = 0.0f;
        {
            float acc = 0.0f;
            #pragma unroll
            for (int i = 0; i < 8; i++) {
                if (i == wid) warp_off = acc;
                acc += s_wsum[i];
            }
            stot = acc;
        }
        float excl = __shfl_up_sync(FULL, incl, 1);
        if (lane == 0) excl = 0.0f;
        const float base = warp_off + excl;

        const float us = u_mult[t] * stot;
        int cnt = (int)((base + p0) < us) + (int)((base + p1) < us)
                + (int)((base + p2) < us) + (int)((base + p3) < us);
        #pragma unroll
        for (int o = 16; o; o >>= 1) cnt += __shfl_xor_sync(FULL, cnt, o);
        if (lane == 0) s_cnt[wid] = cnt;
        __syncthreads();

        if (tid == 0) {
            int total = 0;
            #pragma unroll
            for (int i = 0; i < 8; i++) total += s_cnt[i];
            int loc = (total >= N_NEUR) ? 0 : total;
            g_loc[t] = (unsigned short)loc;

            float c = 0.0f;
            #pragma unroll
            for (int i = 0; i < 8; i++) c += s_ns[i];

            const float thr = ((logf(stot) + c) + LOG_DT_F) - logf(rand_val[t]);
            g_thr[t] = thr;
            // log-space key for the scanner (chunk-local 0.2*t ramp)
            const int cb = (t >> 10) << 10;
            g_q[t] = (thr > 0.0f) ? (__logf(thr) + 0.2f * (float)(t - cb))
                                  : NEG_INF;
            out[IDX_INH + T_STEPS + t] = c;    // noise output
        }

        // zero-fill the out_spikes row (scanner scatters the rare 1.0s)
        reinterpret_cast<float4*>(out)[(size_t)t * (N_NEUR / 4) + tid] =
            make_float4(0.0f, 0.0f, 0.0f, 0.0f);

        // release: one fence + one atomic per block
        __syncthreads();
        if (tid == 0) {
            __threadfence();
            atomicAdd(&g_cnt[(t >> 10) << 5], 1);
        }
        return;
    }

    // ======================= SCANNER (block 0) ==============================
    // F^i table (double-accurate, single fp32 rounding; 0 past underflow)
    for (int i = tid; i <= FTAB; i += THREADS)
        s_fp[i] = (float)exp(-0.2 * (double)i);
    // permanent -inf pads beyond each chunk (staging never overwrites them)
    for (int i = tid; i < WIN; i += THREADS) {
        s_q[0][CHUNK + i] = NEG_INF;
        s_q[1][CHUNK + i] = NEG_INF;
    }
    __syncthreads();

    // prologue: stage chunk 0
    if (tid == 0) {
        while (*((volatile int*)&g_cnt[0]) < CHUNK) __nanosleep(256);
        __threadfence();
    }
    __syncthreads();
    for (int i = tid; i < CHUNK; i += THREADS) {
        s_q[0][i]  = g_q[i];
        s_th[0][i] = g_thr[i];
    }
    __syncthreads();

    // phase-1 state (warp 0; uniform across lanes)
    float A     = 0.0f;     // inh_{s+1}: amplitude right after last spike
    int   s_abs = 0;        // last spike time
    int   p     = 0;        // next undecided step
    int   nsp   = 0;
    const int il = lane << 2;   // this lane's element base within the window

    for (int ch = 0; ch < NCH; ++ch) {
        if (tid < 32) {
            const float* qb   = s_q[ch & 1];
            const float* tb   = s_th[ch & 1];
            const int    cb   = ch * CHUNK;
            const int    cend = cb + CHUNK;

            // conservative candidate floor, ramp from s_abs+1 (R11 fix)
            float Slim = (A == 0.0f) ? NEG_INF
                                     : (SLIMC + 0.2f * (float)(s_abs + 1 - cb));

            while (p < cend) {
                const int p4 = p & ~3;
                const float4 qv =
                    reinterpret_cast<const float4*>(qb)[((p4 - cb) >> 2) + lane];
                const int pr = p - p4;   // 0..3: lane-0 elements below p invalid

                const bool c0 = (qv.x > Slim) & ((il + 0) >= pr);
                const bool c1 = (qv.y > Slim) & ((il + 1) >= pr);
                const bool c2 = (qv.z > Slim) & ((il + 2) >= pr);
                const bool c3 = (qv.w > Slim) & ((il + 3) >= pr);

                const unsigned m0 = __ballot_sync(FULL, c0);
                const unsigned m1 = __ballot_sync(FULL, c1);
                const unsigned m2 = __ballot_sync(FULL, c2);
                const unsigned m3 = __ballot_sync(FULL, c3);

                if (!(m0 | m1 | m2 | m3)) {
                    p = min(p4 + WIN, cend);
                    continue;
                }

                const int j0 = m0 ? (((__ffs(m0) - 1) << 2) | 0) : 0x7fffffff;
                const int j1 = m1 ? (((__ffs(m1) - 1) << 2) | 1) : 0x7fffffff;
                const int j2 = m2 ? (((__ffs(m2) - 1) << 2) | 2) : 0x7fffffff;
                const int j3 = m3 ? (((__ffs(m3) - 1) << 2) | 3) : 0x7fffffff;
                const int tc = p4 + min(min(j0, j1), min(j2, j3));  // < cend (pads)

                // exact verification: inh_tc = fl(A * F^(tc-s_abs-1))  (R11 fix)
                const int   kc = min(max(tc - s_abs - 1, 0), FTAB);
                const float w  = __fmul_rn(A, s_fp[kc]);   // A=0 start: w=0
                const float th = tb[tc - cb];
                if (w < th) {                               // true spike
                    const float An =
                        __fadd_rn(__fmul_rn(w, INH_FACTOR_F), INH_INC_F);
                    if (lane == 0 && nsp < MAXSPK) {
                        g_spk_t[nsp] = tc;
                        g_spk_a[nsp] = An;
                    }
                    nsp++;
                    A     = An;
                    s_abs = tc;
                    Slim  = SLIMC + 0.2f * (float)(tc + 1 - cb);
                }
                p = tc + 1;   // advance regardless of verdict
            }
        } else {
            // warps 1..7: stage chunk ch+1 into the other buffer
            const int cn = ch + 1;
            if (cn < NCH) {
                if (lane == 0) {
                    while (*((volatile int*)&g_cnt[cn << 5]) < CHUNK)
                        __nanosleep(256);
                    __threadfence();
                }
                __syncwarp();
                float* dq = s_q[cn & 1];
                float* dt = s_th[cn & 1];
                const int off = cn * CHUNK;
                for (int i = tid - 32; i < CHUNK; i += THREADS - 32) {
                    dq[i] = g_q[off + i];
                    dt[i] = g_thr[off + i];
                }
            }
        }
        __syncthreads();
    }

    if (tid == 0) s_nspk = min(nsp, MAXSPK);
    __syncthreads();

    // ======================= PHASE 2: reconstruction ========================
    // inhibition[t] = inh_{t+1} = A_s * F^(t - ts_s) for the last spike s with
    // ts_s <= t (0 before the first spike); one-hot scatter at spike times.
    {
        const int ns = s_nspk;
        const int t0 = tid * (T_STEPS / THREADS);
        const int t1 = t0 + (T_STEPS / THREADS);

        int lo = 0, hi = ns;
        while (lo < hi) {
            const int mid = (lo + hi) >> 1;
            if (g_spk_t[mid] < t0) lo = mid + 1; else hi = mid;
        }
        int   s    = lo - 1;
        float A2   = (s >= 0) ? g_spk_a[s] : 0.0f;
        int   bs   = (s >= 0) ? g_spk_t[s] : t0;
        int   next = (s + 1 < ns) ? g_spk_t[s + 1] : 0x7fffffff;

        for (int t = t0; t < t1; ++t) {
            float val;
            if (t == next) {
                ++s;
                A2   = g_spk_a[s];
                bs   = t;
                next = (s + 1 < ns) ? g_spk_t[s + 1] : 0x7fffffff;
                out[(size_t)t * N_NEUR + (int)g_loc[t]] = 1.0f;
                val = A2;
            } else {
                val = __fmul_rn(A2, s_fp[min(t - bs, FTAB)]);
            }
            out[IDX_INH + t] = val;
        }
    }
}

extern "C" void kernel_launch(void* const* d_in, const int* in_sizes, int n_in,
                              void* d_out, int out_size)
{
    const float* inputs     = (const float*)d_in[0];
    const float* noise_rand = (const float*)d_in[1];
    const float* u_mult     = (const float*)d_in[2];
    const float* rand_val   = (const float*)d_in[3];
    float* out = (float*)d_out;

    init_kernel<<<1, 1024>>>();
    fused_kernel<<<T_STEPS + 1, THREADS>>>(inputs, noise_rand, u_mult, rand_val, out);
}